// round 11
// baseline (speedup 1.0000x reference)
#include <cuda_runtime.h>
#include <math.h>

// MatchLoss: per src point (16384x3 f32), is the 2nd-nearest tgt within 1e-3?
// mv = (pd<1e-3)+1e-7, pd = ||src - tgt_2nd + 1e-6||; out = log(1+sum(exp(mv)))
//    = log(1 + (N-m)*e^eps + m*e^(1+eps)),  m = match count.
// Spatial hash, cell = 2.1e-3 >= 2*r_eff: the radius ball fits in a 2x2x2 cell
// block (8 probes/src). OPEN ADDRESSING with inline coords: meta = gen|cellkey,
// pos = coords -> each probe is ONE parallel (meta,pos) load round, no chains.
// Single kernel: insert (gen-stamped, no clear) -> grid barrier -> query with
// 4 threads/src (2 probe cells each, shfl merge). Exact coord fallback for the
// rare d2 <= R2CUT case.
#define NPTS      16384
#define HBITS     16
#define HSIZE     (1 << HBITS)
#define HMASK     (HSIZE - 1)
#define QSPLIT    4
#define THREADS   256
#define NB        (NPTS * QSPLIT / THREADS)   // 256 blocks, single wave

#define EPS_F     1e-7f
#define CELL_F    2.1e-3f
#define INV_CELL  (1.0f / CELL_F)
#define R2CUT     (1.05e-3f * 1.05e-3f)   // = (CELL/2)^2 coverage guarantee
#define RAD2      (1e-3f * 1e-3f)
#define BIG       3.402823466e+38f

#define KEYMASK   ((1ULL << 39) - 1ULL)

__device__ unsigned long long g_meta[HSIZE];   // (gen25<<39)|key39 ; stale gen = empty
__device__ float4             g_pos[HSIZE];    // coords inline (valid iff gen matches)
__device__ int                g_match = 0;
__device__ int                g_bar   = 0;
__device__ int                g_exit  = 0;
__device__ unsigned long long g_gen   = 1;     // bumped by last block each launch

// 13-bit offset-packed per axis (exact for |coord| < ~8.5; wrap is consistent
// between insert and probe, so merged far cells only add true-distance candidates)
__device__ __forceinline__ unsigned long long pack_key(int cx, int cy, int cz) {
    return (((unsigned long long)((cx + 4096) & 0x1FFF)) << 26) |
           (((unsigned long long)((cy + 4096) & 0x1FFF)) << 13) |
            ((unsigned long long)((cz + 4096) & 0x1FFF));
}

__device__ __forceinline__ unsigned int key_hash(unsigned long long key) {
    return (unsigned int)((key * 0x9E3779B97F4A7C15ULL) >> 40) & HMASK;
}

__device__ __forceinline__ void grid_barrier(int target) {
    __syncthreads();
    if (threadIdx.x == 0) {
        __threadfence();
        atomicAdd(&g_bar, 1);
        while (*(volatile int*)&g_bar < target) { }
        __threadfence();
    }
    __syncthreads();
}

__global__ __launch_bounds__(THREADS)
void ml_fused_kernel(const float* __restrict__ src, const float* __restrict__ tgt,
                     float* __restrict__ out) {
    __shared__ int swarp[THREADS / 32];
    const int tid  = threadIdx.x;
    const int lane = tid & 31;
    const int warp = tid >> 5;
    const int g    = blockIdx.x * THREADS + tid;   // 0..65535
    const int q    = g >> 2;                        // src index, 4 lanes each
    const int half = g & 3;                         // probe-group 0..3

    const unsigned long long genv = g_gen & 0x1FFFFFFULL;  // consistent pre-launch

    // ---- Insert tgt points (one lane in four; open addressing, no clear) ----
    if (half == 0) {
        const float x = tgt[3 * q + 0], y = tgt[3 * q + 1], z = tgt[3 * q + 2];
        const int cx = (int)floorf(x * INV_CELL);
        const int cy = (int)floorf(y * INV_CELL);
        const int cz = (int)floorf(z * INV_CELL);
        const unsigned long long key  = pack_key(cx, cy, cz);
        const unsigned long long want = (genv << 39) | key;
        unsigned int s = key_hash(key);
        for (;;) {
            const unsigned long long cur = g_meta[s];
            if ((cur >> 39) == genv) { s = (s + 1) & HMASK; continue; }  // occupied
            if (atomicCAS(&g_meta[s], cur, want) == cur) break;          // claimed
        }
        g_pos[s] = make_float4(x, y, z, 0.0f);
    }

    // ---- Pre-barrier: src-side setup (overlaps barrier latency) ----
    const float px = src[3 * q + 0], py = src[3 * q + 1], pz = src[3 * q + 2];
    const float fx = px * INV_CELL, fy = py * INV_CELL, fz = pz * INV_CELL;
    const int cx = (int)floorf(fx);
    const int cy = (int)floorf(fy);
    const int cz = (int)floorf(fz);
    // base corner of the 2x2x2 block containing the radius ball
    const int bx = cx + ((fx - (float)cx >= 0.5f) ? 0 : -1);
    const int by = cy + ((fy - (float)cy >= 0.5f) ? 0 : -1);
    const int bz = cz + ((fz - (float)cz >= 0.5f) ? 0 : -1);

    // This lane's 2 of the 8 probe cells: p = half*2 + j, bits (x,y,z)
    unsigned long long pkeys[2];
    unsigned int       pslot[2];
    #pragma unroll
    for (int j = 0; j < 2; ++j) {
        const int p   = half * 2 + j;
        pkeys[j] = pack_key(bx + (p >> 2), by + ((p >> 1) & 1), bz + (p & 1));
        pslot[j] = key_hash(pkeys[j]);
    }

    grid_barrier(NB);

    // ---- Query: batched first-round (meta,pos) loads for both cells ----
    unsigned long long mw0 = g_meta[pslot[0]];
    unsigned long long mw1 = g_meta[pslot[1]];
    float4             t0  = g_pos[pslot[0]];
    float4             t1  = g_pos[pslot[1]];

    float d1 = BIG, d2 = BIG;
    #pragma unroll
    for (int j = 0; j < 2; ++j) {
        unsigned long long mw = j ? mw1 : mw0;
        float4             t  = j ? t1  : t0;
        unsigned int       s  = pslot[j];
        const unsigned long long pk = pkeys[j];
        while ((mw >> 39) == genv) {           // occupied slot
            if ((mw & KEYMASK) == pk) {        // point belongs to probe cell
                const float ex = px - t.x, ey = py - t.y, ez = pz - t.z;
                const float dd = fmaf(ex, ex, fmaf(ey, ey, ez * ez));
                d2 = fminf(d2, fmaxf(d1, dd));
                d1 = fminf(d1, dd);
            }
            s  = (s + 1) & HMASK;              // rare continuation
            mw = g_meta[s];
            t  = g_pos[s];
        }
    }

    // Merge top-2 values across the 4 lanes of this src point
    #pragma unroll
    for (int o = 1; o <= 2; o <<= 1) {
        const float o1 = __shfl_xor_sync(0xFFFFFFFFu, d1, o);
        const float o2 = __shfl_xor_sync(0xFFFFFFFFu, d2, o);
        d2 = fminf(fmaxf(d1, o1), fminf(d2, o2));
        d1 = fminf(d1, o1);
    }

    int m = 0;
    if (half == 0 && d2 <= R2CUT) {
        // Rare exact fallback: rescan the 8 cells tracking coords, apply the
        // reference pd test (componentwise +1e-6 before the norm).
        float e1 = BIG, e2 = BIG;
        float q1x = 0, q1y = 0, q1z = 0, q2x = 0, q2y = 0, q2z = 0;
        for (int p = 0; p < 8; ++p) {
            const unsigned long long pk =
                pack_key(bx + (p >> 2), by + ((p >> 1) & 1), bz + (p & 1));
            unsigned int s = key_hash(pk);
            unsigned long long mw = g_meta[s];
            while ((mw >> 39) == genv) {
                if ((mw & KEYMASK) == pk) {
                    const float4 t = g_pos[s];
                    const float ex = px - t.x, ey = py - t.y, ez = pz - t.z;
                    const float dd = fmaf(ex, ex, fmaf(ey, ey, ez * ez));
                    if (dd < e2) {
                        if (dd < e1) {
                            e2 = e1; q2x = q1x; q2y = q1y; q2z = q1z;
                            e1 = dd; q1x = t.x; q1y = t.y; q1z = t.z;
                        } else {
                            e2 = dd; q2x = t.x; q2y = t.y; q2z = t.z;
                        }
                    }
                }
                s  = (s + 1) & HMASK;
                mw = g_meta[s];
            }
        }
        if (e2 <= R2CUT) {
            const float ex = px - q2x + 1e-6f;
            const float ey = py - q2y + 1e-6f;
            const float ez = pz - q2z + 1e-6f;
            if (fmaf(ex, ex, fmaf(ey, ey, ez * ez)) < RAD2) m = 1;
        }
    }

    // Deterministic integer reduction; one atomic per block
    #pragma unroll
    for (int o = 16; o > 0; o >>= 1)
        m += __shfl_down_sync(0xFFFFFFFFu, m, o);
    if (lane == 0) swarp[warp] = m;
    __syncthreads();

    if (tid == 0) {
        int bs = 0;
        #pragma unroll
        for (int w = 0; w < THREADS / 32; ++w) bs += swarp[w];
        if (bs) atomicAdd(&g_match, bs);
        __threadfence();
        // Last block to exit finalizes and restores state for graph replay.
        const int e = atomicAdd(&g_exit, 1);
        if (e == NB - 1) {
            const int mm = *(volatile int*)&g_match;
            const float S = (float)(NPTS - mm) * expf(EPS_F)
                          + (float)mm * expf(1.0f + EPS_F);
            out[0] = logf(1.0f + S);   // softplus(logsumexp(mv))
            g_match = 0;
            g_bar   = 0;
            g_exit  = 0;
            g_gen   = g_gen + 1;       // invalidates all slots for next launch
            __threadfence();
        }
    }
}

extern "C" void kernel_launch(void* const* d_in, const int* in_sizes, int n_in,
                              void* d_out, int out_size) {
    const float* src = (const float*)d_in[0];  // src_coords [16384, 3]
    const float* tgt = (const float*)d_in[1];  // tgt_coords [16384, 3]
    float* out = (float*)d_out;
    ml_fused_kernel<<<NB, THREADS>>>(src, tgt, out);
}